// round 13
// baseline (speedup 1.0000x reference)
#include <cuda_runtime.h>
#include <cstddef>

// DilatedKNN: B=4, N=8192, C=64, K=9, d=2 -> top-18 nearest, slice ::2.
// Output float32. key = max((|s|^2+|q|^2) - 2*dot, 0), dot = one sequential
// fma2 chain over ascending k (bit-identical keys to R10/R11).
//
// R13 = R12 + alignment fix: d2s stride stays 131 (phase-B conflict-free),
// but odd-row transpose stores are scalar (odd*131 float offset is not
// 8B-aligned; the float2 store there caused R12's misaligned-address trap).

#define BATCH 4
#define NPTS  8192
#define CDIM  64
#define KOUT  9
#define KK    18
#define MQ    64      // queries per block
#define TSC   128     // candidate tile rows
#define TPB   128
#define NK2   32

// smem layout (floats):
//  qs : 32 k2 x 33 quads (32 qpairs + pad)   = 4224
//  qw : swapped-query copy                   = 4224
//  U  : union 8384: ssm 32x65 quads (8320) [phase A]
//                   d2s 64x131       (8384) [phase B]
//                   merge lists      (4608) [epilogue]
//  sS : 128
#define SM_QW     4224
#define SM_U      8448
#define SM_SS     (SM_U + 8384)
#define SM_FLOATS (SM_SS + 128)

__device__ __forceinline__ void fma2(unsigned long long& d,
                                     unsigned long long a,
                                     unsigned long long b) {
    asm("fma.rn.f32x2 %0, %1, %2, %0;" : "+l"(d) : "l"(a), "l"(b));
}
__device__ __forceinline__ float2 unpack2(unsigned long long v) {
    float2 r;
    asm("mov.b64 {%0, %1}, %2;" : "=f"(r.x), "=f"(r.y) : "l"(v));
    return r;
}

__global__ void __launch_bounds__(TPB, 3)
knn_kernel(const float* __restrict__ q, float* __restrict__ out) {
    extern __shared__ float smem[];
    float4*     qs4 = (float4*)smem;
    ulonglong2* qsU = (ulonglong2*)smem;
    float4*     qw4 = (float4*)(smem + SM_QW);
    ulonglong2* qwU = (ulonglong2*)(smem + SM_QW);
    float4*     ss4 = (float4*)(smem + SM_U);
    ulonglong2* ssU = (ulonglong2*)(smem + SM_U);
    float*      d2s = smem + SM_U;            // aliases ssm (phase B)
    float*      sS  = smem + SM_SS;

    const int b  = blockIdx.x >> 7;           // 128 blocks per batch
    const int q0 = (blockIdx.x & 127) * MQ;
    const float* qb = q + (size_t)b * NPTS * CDIM;
    const int tid = threadIdx.x;
    const int tx  = tid & 15;                 // cpairs tx+16*cp
    const int ty  = tid >> 4;                 // qpairs ty+8*jp
    const int qi  = tid & 63;                 // phase-B query
    const int h   = tid >> 6;                 // phase-B half (0/1)

    // ---- query tile: pair-interleaved + swapped copy ----
    for (int t = tid; t < 32 * 16; t += TPB) {
        int p = t >> 4, kc = t & 15;
        float4 a = ((const float4*)(qb + (size_t)(q0 + 2 * p) * CDIM))[kc];
        float4 c = ((const float4*)(qb + (size_t)(q0 + 2 * p + 1) * CDIM))[kc];
        qs4[(2 * kc) * 33 + p]     = make_float4(a.x, c.x, a.y, c.y);
        qs4[(2 * kc + 1) * 33 + p] = make_float4(a.z, c.z, a.w, c.w);
        qw4[(2 * kc) * 33 + p]     = make_float4(c.x, a.x, c.y, a.y);
        qw4[(2 * kc + 1) * 33 + p] = make_float4(c.z, a.z, c.w, a.w);
    }
    __syncthreads();

    // my query norm (row qi): sequential fmaf over ascending k
    float sqm = 0.f;
    {
        int p = qi >> 1, e = qi & 1;
#pragma unroll
        for (int j = 0; j < NK2; j++) {
            float4 v = qs4[j * 33 + p];
            float f0 = e ? v.y : v.x;
            float f1 = e ? v.w : v.z;
            sqm = fmaf(f0, f0, sqm);
            sqm = fmaf(f1, f1, sqm);
        }
    }

    float kd[KK];
    int   ki[KK];
#pragma unroll
    for (int j = 0; j < KK; j++) { kd[j] = 3.402823466e38f; ki[j] = 0; }

    for (int c0 = 0; c0 < NPTS; c0 += TSC) {
        __syncthreads();   // previous d2s fully consumed
        for (int t = tid; t < 64 * 16; t += TPB) {
            int p = t >> 4, kc = t & 15;
            float4 a = ((const float4*)(qb + (size_t)(c0 + 2 * p) * CDIM))[kc];
            float4 c = ((const float4*)(qb + (size_t)(c0 + 2 * p + 1) * CDIM))[kc];
            ss4[(2 * kc) * 65 + p]     = make_float4(a.x, c.x, a.y, c.y);
            ss4[(2 * kc + 1) * 65 + p] = make_float4(a.z, c.z, a.w, c.w);
        }
        __syncthreads();

        // candidate norms (row tid), same sequential order
        {
            int p = tid >> 1, e = tid & 1;
            float s = 0.f;
#pragma unroll
            for (int j = 0; j < NK2; j++) {
                float4 v = ss4[j * 65 + p];
                float f0 = e ? v.y : v.x;
                float f1 = e ? v.w : v.z;
                s = fmaf(f0, f0, s);
                s = fmaf(f1, f1, s);
            }
            sS[tid] = s;
        }

        // ---- phase A: 8x8 packed dots ----
        unsigned long long accA[4][4], accB[4][4];
#pragma unroll
        for (int jp = 0; jp < 4; jp++)
#pragma unroll
            for (int cp = 0; cp < 4; cp++) { accA[jp][cp] = 0ull; accB[jp][cp] = 0ull; }

#pragma unroll 4
        for (int k2 = 0; k2 < NK2; k2++) {
            ulonglong2 qa[4], qw[4], sv[4];
#pragma unroll
            for (int jp = 0; jp < 4; jp++) {
                qa[jp] = qsU[k2 * 33 + ty + 8 * jp];
                qw[jp] = qwU[k2 * 33 + ty + 8 * jp];
            }
#pragma unroll
            for (int cp = 0; cp < 4; cp++) sv[cp] = ssU[k2 * 65 + tx + 16 * cp];
#pragma unroll
            for (int jp = 0; jp < 4; jp++)
#pragma unroll
                for (int cp = 0; cp < 4; cp++) {
                    fma2(accA[jp][cp], qa[jp].x, sv[cp].x);  // (qe*se, qo*so) k
                    fma2(accA[jp][cp], qa[jp].y, sv[cp].y);  //               k+1
                    fma2(accB[jp][cp], qw[jp].x, sv[cp].x);  // (qo*se, qe*so) k
                    fma2(accB[jp][cp], qw[jp].y, sv[cp].y);  //               k+1
                }
        }
        __syncthreads();   // all phase-A reads of ssm done -> becomes d2s

        // ---- transpose dots into d2s[q*131 + c] ----
        // even row: float2 ok (qe*131 even). odd row: odd float offset ->
        // NOT 8B-aligned -> two scalar stores (R12's trap fixed here).
#pragma unroll
        for (int jp = 0; jp < 4; jp++)
#pragma unroll
            for (int cp = 0; cp < 4; cp++) {
                float2 A  = unpack2(accA[jp][cp]);  // (qe.se, qo.so)
                float2 Bv = unpack2(accB[jp][cp]);  // (qo.se, qe.so)
                int qe = 2 * (ty + 8 * jp);
                int ce = 2 * (tx + 16 * cp);
                *(float2*)(d2s + qe * 131 + ce) = make_float2(A.x, Bv.y);
                d2s[(qe + 1) * 131 + ce]     = Bv.x;
                d2s[(qe + 1) * 131 + ce + 1] = A.y;
            }
        __syncthreads();   // dots + norms visible

        // ---- phase B: my half-row (64 candidates) ----
        const float* row = d2s + qi * 131 + h * 64;
        const float* ns  = sS + h * 64;
        const int base = c0 + h * 64;
#pragma unroll 4
        for (int s = 0; s < 64; s++) {
            float t   = ns[s] + sqm;
            float d2  = t - 2.0f * row[s];
            float key = fmaxf(d2, 0.0f);
            if (key < kd[KK - 1]) {
                kd[KK - 1] = key;
                ki[KK - 1] = base + s;
#pragma unroll
                for (int j = KK - 1; j >= 1; --j) {
                    if (kd[j] < kd[j - 1]) {
                        float tk = kd[j]; kd[j] = kd[j - 1]; kd[j - 1] = tk;
                        int   ti = ki[j]; ki[j] = ki[j - 1]; ki[j - 1] = ti;
                    }
                }
            }
        }
    }

    // ---- merge the two half-lists per query (stable by (key, idx)) ----
    __syncthreads();                        // last phase B done
    float* mk = smem + SM_U;                // 128 slots x 18 keys
    int*   mi = (int*)(smem + SM_U + 2304); // 128 slots x 18 idx
    {
        int slot = qi * 2 + h;
#pragma unroll
        for (int j = 0; j < KK; j++) {
            mk[slot * KK + j] = kd[j];
            mi[slot * KK + j] = ki[j];
        }
    }
    __syncthreads();
    if (tid < MQ) {
        const float* ka = mk + (tid * 2) * KK;
        const int*   ia = mi + (tid * 2) * KK;
        const float* kb = ka + KK;
        const int*   ib = ia + KK;
        float* orow = out + ((size_t)(b * NPTS + q0 + tid)) * KOUT;
        int pa = 0, pb = 0;
#pragma unroll
        for (int j = 0; j < KK; j++) {
            float k0 = ka[pa], k1 = kb[pb];
            int   i0 = ia[pa], i1 = ib[pb];
            bool takeA = (k0 < k1) || (k0 == k1 && i0 < i1);
            int sel = takeA ? i0 : i1;
            if ((j & 1) == 0) orow[j >> 1] = (float)sel;   // dilated ::2
            pa += takeA ? 1 : 0;
            pb += takeA ? 0 : 1;
        }
    }
}

// ---------------------------------------------------------------------------
extern "C" void kernel_launch(void* const* d_in, const int* in_sizes, int n_in,
                              void* d_out, int out_size) {
    const float* q = (const float*)d_in[0];
    float* out = (float*)d_out;
    size_t smem_bytes = (size_t)SM_FLOATS * sizeof(float);   // ~67.8 KB
    cudaFuncSetAttribute(knn_kernel,
                         cudaFuncAttributeMaxDynamicSharedMemorySize,
                         (int)smem_bytes);
    knn_kernel<<<BATCH * (NPTS / MQ), TPB, smem_bytes>>>(q, out);
}